// round 15
// baseline (speedup 1.0000x reference)
#include <cuda_runtime.h>
#include <cuda_bf16.h>
#include <math.h>

#define N_ANCH 6000
#define N_CLS  81
#define PAD    300
#define MASK_SZ (14*14*81)   // 15876
#define NMS_THRESH 0.5f
#define T      1024
#define GRID   120
#define NW     (GRID * 32)
#define TARGET 384u
#define KEYCAP 8192
#define CH     512
#define MAT_STRIDE 516
#define NK     ((N_ANCH + T - 1) / T)   // 6 score slots per thread

// ---- dynamic smem layout (bytes) ----
#define OFF_KEYS  131072   // u64[8192]  (65536) -> 196608
#define OFF_S1    196608   // u32[1024]  (4096)  -> 200704
#define OFF_KBOX  200704   // float4[300](4800)  -> 205504
#define OFF_KAREA 205504   // f32[300]   (1200)  -> 206704
#define OFF_SCAL  206704
#define SMEM_TOTAL 206848
// region A aliases (strict phase lifetimes):
//   hist u32[32768]@0 (131072)          -- block-0 select ONLY
//   cbox f4[512]@0 | carea f32[512]@8192 | sprev u32[512]@10240
//   cidx u32[512]@12288 | mat u32[16*516]@14336 (33024)   -- phase2+/fallback
//   smat u32[16*512]@47360 (32768) | scidx u32[512]@80128 -- resolve ONLY

// ---------------- scratch (device globals, no allocation) ----------------
__device__ float  g_nscore[N_ANCH];
__device__ int    g_cls[N_ANCH];
__device__ unsigned long long g_skeys[KEYCAP];
__device__ int      g_S;
__device__ unsigned g_lo;
__device__ unsigned g_mat[16 * 512];
__device__ int    g_idx[PAD];
__device__ float  g_valid[PAD];
__device__ float4 g_obox[PAD];
__device__ int c_dec, f_sel, c_mat, f_res, c_fin;

__device__ __forceinline__ void spin_ge(int* c, int v)
{
    if (threadIdx.x == 0) {
        while (*(volatile int*)c < v) __nanosleep(64);
        __threadfence();
    }
    __syncthreads();
}
__device__ __forceinline__ void signal(int* c)
{
    __syncthreads();
    if (threadIdx.x == 0) { __threadfence(); atomicAdd(c, 1); }
}

__device__ __forceinline__ bool iou_sup(float4 a, float aa, float4 b, float ba)
{
    float xx1 = fmaxf(a.x, b.x);
    float yy1 = fmaxf(a.y, b.y);
    float xx2 = fminf(a.z, b.z);
    float yy2 = fminf(a.w, b.w);
    float iw = fmaxf(xx2 - xx1 + 1.0f, 0.0f);
    float ih = fmaxf(yy2 - yy1 + 1.0f, 0.0f);
    float inter = iw * ih;
    return inter / (aa + ba - inter) > NMS_THRESH;
}

__device__ __forceinline__ float4 decode_box(int a,
    const float* __restrict__ meta,
    const float* __restrict__ deltas,
    const float* __restrict__ props)
{
    float H = meta[0], W = meta[1], scale = meta[2];
    const float* p = props + (size_t)a * 4;
    float x1 = p[0] / scale, y1 = p[1] / scale;
    float x2 = p[2] / scale, y2 = p[3] / scale;
    float w  = x2 - x1 + 1.0f, h = y2 - y1 + 1.0f;
    float cx = x1 + 0.5f * w, cy = y1 + 0.5f * h;

    int bc = g_cls[a];
    const float* d = deltas + (size_t)a * (4 * N_CLS) + bc * 4;
    float pcx = d[0] * w + cx;
    float pcy = d[1] * h + cy;
    float pw  = expf(d[2]) * w;
    float ph  = expf(d[3]) * h;

    float px1 = pcx - 0.5f * pw, py1 = pcy - 0.5f * ph;
    float px2 = pcx + 0.5f * pw, py2 = pcy + 0.5f * ph;
    px1 = fminf(fmaxf(px1, 0.0f), W - 1.0f);
    py1 = fminf(fmaxf(py1, 0.0f), H - 1.0f);
    px2 = fminf(fmaxf(px2, 0.0f), W - 1.0f);
    py2 = fminf(fmaxf(py2, 0.0f), H - 1.0f);
    return make_float4(px1, py1, px2, py2);
}

// fine bucket for single-pass first select: mantissa bits [22:7] of scores in
// [0.5, 1.0); clamped outside. Monotone in score bits by construction.
__device__ __forceinline__ unsigned fine_bucket(unsigned bits)
{
    if (bits >= 0x3F800000u) return 65535u;
    if (bits <  0x3F000000u) return 0u;
    return (bits >> 7) - 0x7E0000u;
}

// warp-0 hierarchical suffix search over 65536-bucket histogram.
__device__ __forceinline__ void warp_select(const unsigned* hist, const unsigned* s1,
                                            unsigned target,
                                            volatile unsigned* s_b,
                                            volatile unsigned* s_above,
                                            volatile int* s_all)
{
    int lane = threadIdx.x;

    unsigned s2 = 0;
    #pragma unroll 8
    for (int q = 0; q < 32; q++) s2 += s1[lane * 32 + q];
    unsigned incl = s2;
    #pragma unroll
    for (int off = 1; off < 32; off <<= 1) {
        unsigned v = __shfl_down_sync(0xffffffffu, incl, off);
        if (lane + off < 32) incl += v;
    }
    unsigned total = __shfl_sync(0xffffffffu, incl, 0);
    if (total < target) { if (lane == 0) *s_all = 1; return; }
    if (lane == 0) *s_all = 0;

    unsigned bal = __ballot_sync(0xffffffffu, incl >= target);
    int L1 = 31 - __clz(bal);
    unsigned carry1 = __shfl_sync(0xffffffffu, incl, (L1 + 1) & 31);
    if (L1 == 31) carry1 = 0;

    incl = s1[L1 * 32 + lane];
    #pragma unroll
    for (int off = 1; off < 32; off <<= 1) {
        unsigned v = __shfl_down_sync(0xffffffffu, incl, off);
        if (lane + off < 32) incl += v;
    }
    bal = __ballot_sync(0xffffffffu, carry1 + incl >= target);
    int L2 = 31 - __clz(bal);
    unsigned carry2 = __shfl_sync(0xffffffffu, incl, (L2 + 1) & 31);
    if (L2 == 31) carry2 = 0;
    carry2 += carry1;

    int bbase = (L1 * 32 + L2) * 64;
    unsigned w = hist[(bbase >> 1) + lane];
    unsigned lowc = w & 0xFFFFu, highc = w >> 16;
    incl = lowc + highc;
    #pragma unroll
    for (int off = 1; off < 32; off <<= 1) {
        unsigned v = __shfl_down_sync(0xffffffffu, incl, off);
        if (lane + off < 32) incl += v;
    }
    bal = __ballot_sync(0xffffffffu, carry2 + incl >= target);
    int L3 = 31 - __clz(bal);
    unsigned carryn = __shfl_sync(0xffffffffu, incl, (L3 + 1) & 31);
    if (L3 == 31) carryn = 0;
    carryn += carry2;

    if (lane == L3) {
        unsigned b, ab;
        if (carryn + highc >= target) { b = (unsigned)(bbase + 2 * L3 + 1); ab = carryn; }
        else                          { b = (unsigned)(bbase + 2 * L3);     ab = carryn + highc; }
        *s_b = b; *s_above = ab;
    }
}

// general two-pass radix select (fallback rounds only) — exact for arbitrary hi
__device__ unsigned radix_threshold(unsigned* hist, unsigned* s1, unsigned hi, unsigned target,
                                    volatile unsigned* s_b, volatile unsigned* s_above,
                                    volatile int* s_all)
{
    const int tid = threadIdx.x;
    for (int i = tid; i < 8192; i += T) ((uint4*)hist)[i] = make_uint4(0, 0, 0, 0);
    __syncthreads();
    for (int i = tid; i < N_ANCH; i += T) {
        unsigned bits = __float_as_uint(g_nscore[i]);
        if (bits <= hi) {
            unsigned b = bits >> 16;
            atomicAdd(&hist[b >> 1], 1u << ((b & 1) * 16));
        }
    }
    __syncthreads();
    {
        unsigned s = 0;
        #pragma unroll 8
        for (int q = 0; q < 32; q++) { unsigned w = hist[tid * 32 + q]; s += (w & 0xFFFFu) + (w >> 16); }
        s1[tid] = s;
    }
    __syncthreads();
    if (tid < 32) warp_select(hist, s1, target, s_b, s_above, s_all);
    __syncthreads();

    unsigned lo;
    if (*s_all) {
        lo = 0u;
    } else {
        unsigned b1  = *s_b;
        unsigned chi = *s_above;
        __syncthreads();
        for (int i = tid; i < 8192; i += T) ((uint4*)hist)[i] = make_uint4(0, 0, 0, 0);
        __syncthreads();
        for (int i = tid; i < N_ANCH; i += T) {
            unsigned bits = __float_as_uint(g_nscore[i]);
            if (bits <= hi && (bits >> 16) == b1) {
                unsigned b = bits & 0xFFFFu;
                atomicAdd(&hist[b >> 1], 1u << ((b & 1) * 16));
            }
        }
        __syncthreads();
        {
            unsigned s = 0;
            #pragma unroll 8
            for (int q = 0; q < 32; q++) { unsigned w = hist[tid * 32 + q]; s += (w & 0xFFFFu) + (w >> 16); }
            s1[tid] = s;
        }
        __syncthreads();
        if (tid < 32) warp_select(hist, s1, target - chi, s_b, s_above, s_all);
        __syncthreads();
        lo = (*s_all) ? (b1 << 16) : ((b1 << 16) | *s_b);
    }
    __syncthreads();
    return lo;
}

// sort keys[0..S) descending in smem (rank-sort fast path, bitonic fallback)
__device__ void sort_keys(unsigned long long* keys, int S)
{
    const int tid = threadIdx.x;
    if (S <= T) {
        unsigned long long mykey = (tid < S) ? keys[tid] : 0ull;
        int rank = 0;
        if (tid < S) {
            for (int j = 0; j < S; j++) rank += (keys[j] > mykey) ? 1 : 0;
        }
        __syncthreads();
        if (tid < S) keys[rank] = mykey;
        __syncthreads();
    } else {
        int nsort = 1024;
        while (nsort < S) nsort <<= 1;
        for (int i = tid; i < nsort; i += T) if (i >= S) keys[i] = 0ull;
        __syncthreads();
        for (int k = 2; k <= nsort; k <<= 1) {
            for (int j = k >> 1; j > 0; j >>= 1) {
                for (int i = tid; i < nsort; i += T) {
                    int ixj = i ^ j;
                    if (ixj > i) {
                        unsigned long long a = keys[i], b = keys[ixj];
                        bool up = ((i & k) == 0);
                        if (up ? (a < b) : (a > b)) { keys[i] = b; keys[ixj] = a; }
                    }
                }
                __syncthreads();
            }
        }
    }
}

// collect (general, for fallback rounds) + sort
__device__ int collect_sort(unsigned long long* keys, unsigned lo, unsigned hi,
                            volatile unsigned* s_cnt)
{
    const int tid = threadIdx.x;
    if (tid == 0) *s_cnt = 0;
    __syncthreads();
    for (int i = tid; i < N_ANCH; i += T) {
        unsigned bits = __float_as_uint(g_nscore[i]);
        if (bits >= lo && bits <= hi) {
            unsigned p = atomicAdd((unsigned*)s_cnt, 1u);
            if (p < KEYCAP)
                keys[p] = ((unsigned long long)bits << 32) | (0xFFFFFFFFu - (unsigned)i);
        }
    }
    __syncthreads();
    int S = min((int)*s_cnt, KEYCAP);
    sort_keys(keys, S);
    return S;
}

// general (slow-path) chunk processor — candidates beyond the first CH only
__device__ int nms_chunk(int cn, int kept,
                         float4* cbox, float* carea, unsigned* sprev, unsigned* cidx,
                         unsigned* mat, float4* kbox, float* karea, volatile int* s_kept)
{
    const int tid = threadIdx.x;
    const int lane = tid & 31;

    if (kept == 0) {
        for (int c = tid; c < cn; c += T) sprev[c] = 0;
    } else {
        for (int c = tid; c < cn; c += T) {
            float4 b = cbox[c]; float ba = carea[c];
            unsigned f = 0;
            for (int q = 0; q < kept; q++)
                if (iou_sup(kbox[q], karea[q], b, ba)) { f = 1; break; }
            sprev[c] = f;
        }
    }

    for (int iw = tid; iw < CH * 16; iw += T) {
        int i = iw & (CH - 1);
        int w = iw >> 9;
        int j0 = w << 5;
        if (i < cn && j0 < i) {
            float4 bi = cbox[i]; float ai = carea[i];
            int jmax = min(i, j0 + 32);
            unsigned word = 0;
            for (int j = j0; j < jmax; j++)
                if (iou_sup(cbox[j], carea[j], bi, ai)) word |= 1u << (j - j0);
            mat[w * MAT_STRIDE + i] = word;
        } else if (i < cn) {
            mat[w * MAT_STRIDE + i] = 0u;
        }
    }
    __syncthreads();

    if (tid < 32) {
        unsigned km = 0;
        int kp = kept;
        unsigned row = (lane < 16 && cn > 0) ? mat[lane * MAT_STRIDE] : 0u;
        for (int i = 0; i < cn && kp < PAD; i++) {
            unsigned nrow = (lane < 16 && i + 1 < cn) ? mat[lane * MAT_STRIDE + i + 1] : 0u;
            unsigned sp = sprev[i];
            bool clash = __any_sync(0xffffffffu, (row & km) != 0u) || (sp != 0u);
            if (!clash) {
                if (lane == 0) {
                    g_idx[kp]   = (int)cidx[i];
                    g_valid[kp] = 1.0f;
                    g_obox[kp]  = cbox[i];
                    kbox[kp]    = cbox[i];
                    karea[kp]   = carea[i];
                }
                if (lane == (i >> 5)) km |= 1u << (i & 31);
                kp++;
            }
            row = nrow;
        }
        if (lane == 0) *s_kept = kp;
    }
    __syncthreads();
    return *s_kept;
}

// ---------------- output layout ----------------
#define OFF_SC  (PAD * 4)
#define OFF_MK  (OFF_SC + PAD * N_CLS)
#define PER_F4  (MASK_SZ / 4)   // 3969

// ---------------- THE mega-kernel ----------------
__global__ __launch_bounds__(T, 1) void k_mega(
    const float* __restrict__ meta,
    const float* __restrict__ deltas,
    const float* __restrict__ props,
    const float* __restrict__ scores,
    const float* __restrict__ masks,
    float* __restrict__ out)
{
    extern __shared__ char sm[];
    unsigned*           hist  = (unsigned*)(sm);
    float4*             cbox  = (float4*)(sm);
    float*              carea = (float*)(sm + 8192);
    unsigned*           sprev = (unsigned*)(sm + 10240);
    unsigned*           cidx  = (unsigned*)(sm + 12288);
    unsigned*           mat   = (unsigned*)(sm + 14336);
    unsigned*           smat  = (unsigned*)(sm + 47360);   // [16][512] -- resolve only
    unsigned*           scidx = (unsigned*)(sm + 80128);   // [512]
    unsigned long long* keys  = (unsigned long long*)(sm + OFF_KEYS);
    unsigned*           s1    = (unsigned*)(sm + OFF_S1);
    float4*             kbox  = (float4*)(sm + OFF_KBOX);
    float*              karea = (float*)(sm + OFF_KAREA);
    volatile unsigned*  s_cnt   = (volatile unsigned*)(sm + OFF_SCAL);
    volatile int*       s_kept  = (volatile int*)(sm + OFF_SCAL + 4);
    volatile unsigned*  s_b     = (volatile unsigned*)(sm + OFF_SCAL + 8);
    volatile unsigned*  s_above = (volatile unsigned*)(sm + OFF_SCAL + 12);
    volatile int*       s_all   = (volatile int*)(sm + OFF_SCAL + 16);

    const int tid  = threadIdx.x;
    const int lane = tid & 31;
    const int bid  = blockIdx.x;
    const int gtid = bid * T + tid;

    // ========= phase 0: score scan (all blocks, warp per anchor) =========
    {
        int gw = bid * 32 + (tid >> 5);
        for (int a = gw; a < N_ANCH; a += NW) {
            const float* srow = scores + (size_t)a * N_CLS;
            float bv = -INFINITY; int bc = 0;
            float ms = -INFINITY;
            for (int c = lane; c < N_CLS; c += 32) {
                float v = srow[c];
                if (v > bv) { bv = v; bc = c; }
                if (c >= 1) ms = fmaxf(ms, v);
            }
            #pragma unroll
            for (int off = 16; off; off >>= 1) {
                float ov  = __shfl_down_sync(0xffffffffu, bv, off);
                int   oc  = __shfl_down_sync(0xffffffffu, bc, off);
                float oms = __shfl_down_sync(0xffffffffu, ms, off);
                if (ov > bv || (ov == bv && oc < bc)) { bv = ov; bc = oc; }
                ms = fmaxf(ms, oms);
            }
            if (lane == 0) {
                g_nscore[a] = ms;
                g_cls[a]    = bc;
            }
        }
        for (int i = gtid; i < 16 * 512; i += GRID * T) g_mat[i] = 0u;
    }
    signal(&c_dec);

    // ========= phase 1: single-pass select + sort (block 0 only) =========
    if (bid == 0) {
        spin_ge(&c_dec, GRID);

        // load score bits once into registers
        unsigned mybits[NK];
        #pragma unroll
        for (int k = 0; k < NK; k++) {
            int i = tid + k * T;
            mybits[k] = (i < N_ANCH) ? __float_as_uint(g_nscore[i]) : 0u;
        }

        // fine histogram
        for (int i = tid; i < 8192; i += T) ((uint4*)hist)[i] = make_uint4(0, 0, 0, 0);
        __syncthreads();
        #pragma unroll
        for (int k = 0; k < NK; k++) {
            int i = tid + k * T;
            if (i < N_ANCH) {
                unsigned b = fine_bucket(mybits[k]);
                atomicAdd(&hist[b >> 1], 1u << ((b & 1) * 16));
            }
        }
        __syncthreads();
        {
            unsigned s = 0;
            #pragma unroll 8
            for (int q = 0; q < 32; q++) { unsigned w = hist[tid * 32 + q]; s += (w & 0xFFFFu) + (w >> 16); }
            s1[tid] = s;
        }
        __syncthreads();
        if (tid < 32) warp_select(hist, s1, TARGET, s_b, s_above, s_all);
        __syncthreads();

        unsigned lo;
        if (*s_all) lo = 0u;
        else {
            unsigned b = *s_b;
            lo = (b == 0u) ? 0u : (0x3F000000u + (b << 7));
        }
        __syncthreads();

        // collect from register cache
        if (tid == 0) *s_cnt = 0;
        __syncthreads();
        #pragma unroll
        for (int k = 0; k < NK; k++) {
            int i = tid + k * T;
            if (i < N_ANCH && mybits[k] >= lo) {
                unsigned p = atomicAdd((unsigned*)s_cnt, 1u);
                if (p < KEYCAP)
                    keys[p] = ((unsigned long long)mybits[k] << 32) | (0xFFFFFFFFu - (unsigned)i);
            }
        }
        __syncthreads();
        int S = min((int)*s_cnt, KEYCAP);
        sort_keys(keys, S);

        for (int i = tid; i < S; i += T) g_skeys[i] = keys[i];
        __syncthreads();
        if (tid == 0) { g_S = S; g_lo = lo; __threadfence(); atomicExch(&f_sel, 1); }
        __syncthreads();
    }

    // ========= phase 2: candidate decode + bitmatrix (overlapped) =========
    spin_ge(&f_sel, 1);
    {
        int cn = min(g_S, CH);
        if (bid == 0) {
            // block 0: decode candidates into its own smem for resolve/output
            for (int c = tid; c < cn; c += T) {
                int aidx = (int)(0xFFFFFFFFu - (unsigned)keys[c]);
                float4 b = decode_box(aidx, meta, deltas, props);
                cbox[c]  = b;
                carea[c] = (b.z - b.x + 1.0f) * (b.w - b.y + 1.0f);
            }
        } else {
            // other blocks: decode into local smem, then matrix from LDS
            for (int c = tid; c < cn; c += T) {
                int aidx = (int)(0xFFFFFFFFu - (unsigned)g_skeys[c]);
                float4 b = decode_box(aidx, meta, deltas, props);
                cbox[c]  = b;
                carea[c] = (b.z - b.x + 1.0f) * (b.w - b.y + 1.0f);
            }
            __syncthreads();
            int npair = cn * (cn - 1) / 2;
            for (int p = (bid - 1) * T + tid; p < npair; p += (GRID - 1) * T) {
                float q = sqrtf((float)(8 * p + 1));
                int i = (int)((1.0f + q) * 0.5f);
                while (i * (i - 1) / 2 > p) i--;
                while ((i + 1) * i / 2 <= p) i++;
                int j = p - i * (i - 1) / 2;

                if (iou_sup(cbox[j], carea[j], cbox[i], carea[i]))
                    atomicOr(&g_mat[(j >> 5) * 512 + i], 1u << (j & 31));
            }
        }
    }
    signal(&c_mat);

    // ========= phase 3: resolve (block 0 only) =========
    if (bid == 0) {
        spin_ge(&c_mat, GRID);

        int S = g_S;
        int cn0 = min(S, CH);

        for (int i = tid; i < 2048; i += T) ((uint4*)smat)[i] = ((const uint4*)g_mat)[i];
        for (int i = tid; i < cn0; i += T) scidx[i] = 0xFFFFFFFFu - (unsigned)keys[i];
        if (tid == 0) *s_kept = 0;
        __syncthreads();

        if (tid < 32) {
            unsigned km[16];
            #pragma unroll
            for (int g = 0; g < 16; g++) km[g] = 0u;
            int kp = 0;

            #pragma unroll
            for (int g = 0; g < 16; g++) {
                if (kp >= PAD) break;
                int i = g * 32 + lane;
                bool active = i < cn0;
                unsigned r = active ? smat[g * 512 + i] : 0u;
                unsigned clash = 0;
                #pragma unroll
                for (int w = 0; w < 16; w++) {
                    if (w >= g) break;
                    clash |= (active ? smat[w * 512 + i] : 0u) & km[w];
                }
                unsigned myidx = active ? scidx[i] : 0u;

                unsigned activeM  = __ballot_sync(0xffffffffu, active);
                unsigned suspects = __ballot_sync(0xffffffffu, active && ((r != 0u) || (clash != 0u)));

                unsigned kmg;
                if (suspects == 0u) {
                    kmg = activeM;
                } else {
                    kmg = activeM & ~suspects;
                    unsigned rem = suspects;
                    while (rem) {
                        int t = __ffs(rem) - 1; rem &= rem - 1;
                        unsigned rt = __shfl_sync(0xffffffffu, r, t);
                        unsigned ct = __shfl_sync(0xffffffffu, clash, t);
                        if (ct == 0u && (rt & kmg) == 0u) kmg |= 1u << t;
                    }
                }

                int allowed = PAD - kp;
                int cnt = __popc(kmg);
                int rank = __popc(kmg & ((1u << lane) - 1u));
                bool mykeep = ((kmg >> lane) & 1u) && (rank < allowed);
                if (mykeep) {
                    g_idx[kp + rank]   = (int)myidx;
                    g_valid[kp + rank] = 1.0f;
                    g_obox[kp + rank]  = cbox[i];
                }
                km[g] = __ballot_sync(0xffffffffu, mykeep);
                kp += min(cnt, allowed);
            }
            if (lane == 0) *s_kept = kp;
        }
        __syncthreads();
        int kept = *s_kept;

        // general fallback (rare): more chunks / further radix rounds
        if (kept < PAD && (S > CH || g_lo > 0)) {
            for (int q = tid; q < kept; q += T) {
                float4 b = g_obox[q];
                kbox[q] = b;
                karea[q] = (b.z - b.x + 1.0f) * (b.w - b.y + 1.0f);
            }
            __syncthreads();

            for (int base = CH; base < S && kept < PAD; base += CH) {
                int cn = min(CH, S - base);
                for (int c = tid; c < cn; c += T) {
                    int aidx = (int)(0xFFFFFFFFu - (unsigned)keys[base + c]);
                    cidx[c] = (unsigned)aidx;
                    float4 b = decode_box(aidx, meta, deltas, props);
                    cbox[c] = b;
                    carea[c] = (b.z - b.x + 1.0f) * (b.w - b.y + 1.0f);
                }
                __syncthreads();
                kept = nms_chunk(cn, kept, cbox, carea, sprev, cidx, mat,
                                 kbox, karea, s_kept);
            }

            if (kept < PAD && g_lo > 0) {
                unsigned hi = g_lo - 1u;
                while (kept < PAD) {
                    unsigned lo = radix_threshold(hist, s1, hi, TARGET, s_b, s_above, s_all);
                    int Sb = collect_sort(keys, lo, hi, s_cnt);
                    for (int base = 0; base < Sb && kept < PAD; base += CH) {
                        int cn = min(CH, Sb - base);
                        for (int c = tid; c < cn; c += T) {
                            int aidx = (int)(0xFFFFFFFFu - (unsigned)keys[base + c]);
                            cidx[c] = (unsigned)aidx;
                            float4 b = decode_box(aidx, meta, deltas, props);
                            cbox[c] = b;
                            carea[c] = (b.z - b.x + 1.0f) * (b.w - b.y + 1.0f);
                        }
                        __syncthreads();
                        kept = nms_chunk(cn, kept, cbox, carea, sprev, cidx, mat,
                                         kbox, karea, s_kept);
                    }
                    if (lo == 0u) break;
                    hi = lo - 1u;
                    __syncthreads();
                }
            }
        }

        for (int r = kept + tid; r < PAD; r += T) { g_idx[r] = 0; g_valid[r] = 0.0f; }
        __syncthreads();
        if (tid == 0) { __threadfence(); atomicExch(&f_res, 1); }
        __syncthreads();
    }

    // ========= phase 4: gather (all blocks) =========
    spin_ge(&f_res, 1);
    {
        for (int d = bid; d < PAD; d += GRID) {
            int idx = g_idx[d];
            float s = g_valid[d];
            const float4* src = (const float4*)(masks + (size_t)idx * MASK_SZ);
            float4* dst = (float4*)(out + OFF_MK) + (size_t)d * PER_F4;
            for (int m = tid; m < PER_F4; m += T) {
                float4 v = src[m];
                v.x *= s; v.y *= s; v.z *= s; v.w *= s;
                dst[m] = v;
            }
        }
        if (gtid < OFF_MK) {
            int e = gtid;
            if (e < OFF_SC) {
                int k = e >> 2, c = e & 3;
                const float* bp = (const float*)&g_obox[k];
                out[e] = bp[c] * g_valid[k];
            } else {
                int r = e - OFF_SC;
                int k = r / N_CLS, c = r - k * N_CLS;
                out[e] = scores[(size_t)g_idx[k] * N_CLS + c] * g_valid[k];
            }
        }
    }
    signal(&c_fin);

    // ========= phase 5: reset counters for next graph replay =========
    if (bid == 0) {
        if (tid == 0) {
            while (*(volatile int*)&c_fin < GRID) __nanosleep(64);
            c_dec = 0; f_sel = 0; c_mat = 0; f_res = 0; c_fin = 0;
            __threadfence();
        }
    }
}

// ---------------- launch ----------------
extern "C" void kernel_launch(void* const* d_in, const int* in_sizes, int n_in,
                              void* d_out, int out_size)
{
    const float* meta   = (const float*)d_in[0];
    const float* deltas = (const float*)d_in[1];
    const float* props  = (const float*)d_in[2];
    const float* scores = (const float*)d_in[3];
    const float* masks  = (const float*)d_in[4];
    float* out = (float*)d_out;

    static bool attr_done = false;
    if (!attr_done) {
        cudaFuncSetAttribute(k_mega, cudaFuncAttributeMaxDynamicSharedMemorySize, SMEM_TOTAL);
        attr_done = true;
    }

    k_mega<<<GRID, T, SMEM_TOTAL>>>(meta, deltas, props, scores, masks, out);
}

// round 16
// speedup vs baseline: 1.4297x; 1.4297x over previous
#include <cuda_runtime.h>
#include <cuda_bf16.h>
#include <math.h>

#define N_ANCH 6000
#define N_CLS  81
#define PAD    300
#define MASK_SZ (14*14*81)   // 15876
#define NMS_THRESH 0.5f
#define T      1024
#define GRID   120
#define NW     (GRID * 32)
#define TARGET 384u
#define KEYCAP 8192
#define CH     512
#define MAT_STRIDE 516
#define NK     ((N_ANCH + T - 1) / T)   // 6 score slots per thread

// ---- dynamic smem layout (bytes) ----
#define OFF_KEYS  131072   // u64[8192]  (65536) -> 196608
#define OFF_S1    196608   // u32[1024]  (4096)  -> 200704
#define OFF_KBOX  200704   // float4[300](4800)  -> 205504
#define OFF_KAREA 205504   // f32[300]   (1200)  -> 206704
#define OFF_SCAL  206704
#define SMEM_TOTAL 206848
// region A aliases (strict phase lifetimes):
//   hist u32[32768]@0 (131072)          -- block-0 select ONLY
//   cbox f4[512]@0 | carea f32[512]@8192 | sprev u32[512]@10240
//   cidx u32[512]@12288 | mat u32[16*516]@14336 (33024)   -- fallback chunks
//   smat u32[16*512]@47360 (32768) | scidx u32[512]@80128 -- resolve ONLY

// ---------------- scratch (device globals, no allocation) ----------------
__device__ float  g_nscore[N_ANCH];
__device__ int    g_cls[N_ANCH];
__device__ unsigned long long g_skeys[KEYCAP];
__device__ float4 g_cbox[CH];
__device__ float  g_carea[CH];
__device__ int      g_S;
__device__ unsigned g_lo;
__device__ unsigned g_mat[16 * 512];
__device__ int    g_idx[PAD];
__device__ float  g_valid[PAD];
__device__ float4 g_obox[PAD];
__device__ int c_dec, f_sel, c_mat, f_res, c_fin;

__device__ __forceinline__ void spin_ge(int* c, int v)
{
    if (threadIdx.x == 0) {
        while (*(volatile int*)c < v) __nanosleep(64);
        __threadfence();
    }
    __syncthreads();
}
__device__ __forceinline__ void signal(int* c)
{
    __syncthreads();
    if (threadIdx.x == 0) { __threadfence(); atomicAdd(c, 1); }
}

__device__ __forceinline__ bool iou_sup(float4 a, float aa, float4 b, float ba)
{
    float xx1 = fmaxf(a.x, b.x);
    float yy1 = fmaxf(a.y, b.y);
    float xx2 = fminf(a.z, b.z);
    float yy2 = fminf(a.w, b.w);
    float iw = fmaxf(xx2 - xx1 + 1.0f, 0.0f);
    float ih = fmaxf(yy2 - yy1 + 1.0f, 0.0f);
    float inter = iw * ih;
    return inter / (aa + ba - inter) > NMS_THRESH;
}

__device__ __forceinline__ float4 decode_box(int a,
    const float* __restrict__ meta,
    const float* __restrict__ deltas,
    const float* __restrict__ props)
{
    float H = meta[0], W = meta[1], scale = meta[2];
    const float* p = props + (size_t)a * 4;
    float x1 = p[0] / scale, y1 = p[1] / scale;
    float x2 = p[2] / scale, y2 = p[3] / scale;
    float w  = x2 - x1 + 1.0f, h = y2 - y1 + 1.0f;
    float cx = x1 + 0.5f * w, cy = y1 + 0.5f * h;

    int bc = g_cls[a];
    const float* d = deltas + (size_t)a * (4 * N_CLS) + bc * 4;
    float pcx = d[0] * w + cx;
    float pcy = d[1] * h + cy;
    float pw  = expf(d[2]) * w;
    float ph  = expf(d[3]) * h;

    float px1 = pcx - 0.5f * pw, py1 = pcy - 0.5f * ph;
    float px2 = pcx + 0.5f * pw, py2 = pcy + 0.5f * ph;
    px1 = fminf(fmaxf(px1, 0.0f), W - 1.0f);
    py1 = fminf(fmaxf(py1, 0.0f), H - 1.0f);
    px2 = fminf(fmaxf(px2, 0.0f), W - 1.0f);
    py2 = fminf(fmaxf(py2, 0.0f), H - 1.0f);
    return make_float4(px1, py1, px2, py2);
}

// fine bucket for single-pass first select: mantissa bits [22:7] of scores in
// [0.5, 1.0); clamped outside. Monotone in score bits by construction.
__device__ __forceinline__ unsigned fine_bucket(unsigned bits)
{
    if (bits >= 0x3F800000u) return 65535u;
    if (bits <  0x3F000000u) return 0u;
    return (bits >> 7) - 0x7E0000u;
}

// warp-0 hierarchical suffix search over 65536-bucket histogram.
__device__ __forceinline__ void warp_select(const unsigned* hist, const unsigned* s1,
                                            unsigned target,
                                            volatile unsigned* s_b,
                                            volatile unsigned* s_above,
                                            volatile int* s_all)
{
    int lane = threadIdx.x;

    unsigned s2 = 0;
    #pragma unroll 8
    for (int q = 0; q < 32; q++) s2 += s1[lane * 32 + q];
    unsigned incl = s2;
    #pragma unroll
    for (int off = 1; off < 32; off <<= 1) {
        unsigned v = __shfl_down_sync(0xffffffffu, incl, off);
        if (lane + off < 32) incl += v;
    }
    unsigned total = __shfl_sync(0xffffffffu, incl, 0);
    if (total < target) { if (lane == 0) *s_all = 1; return; }
    if (lane == 0) *s_all = 0;

    unsigned bal = __ballot_sync(0xffffffffu, incl >= target);
    int L1 = 31 - __clz(bal);
    unsigned carry1 = __shfl_sync(0xffffffffu, incl, (L1 + 1) & 31);
    if (L1 == 31) carry1 = 0;

    incl = s1[L1 * 32 + lane];
    #pragma unroll
    for (int off = 1; off < 32; off <<= 1) {
        unsigned v = __shfl_down_sync(0xffffffffu, incl, off);
        if (lane + off < 32) incl += v;
    }
    bal = __ballot_sync(0xffffffffu, carry1 + incl >= target);
    int L2 = 31 - __clz(bal);
    unsigned carry2 = __shfl_sync(0xffffffffu, incl, (L2 + 1) & 31);
    if (L2 == 31) carry2 = 0;
    carry2 += carry1;

    int bbase = (L1 * 32 + L2) * 64;
    unsigned w = hist[(bbase >> 1) + lane];
    unsigned lowc = w & 0xFFFFu, highc = w >> 16;
    incl = lowc + highc;
    #pragma unroll
    for (int off = 1; off < 32; off <<= 1) {
        unsigned v = __shfl_down_sync(0xffffffffu, incl, off);
        if (lane + off < 32) incl += v;
    }
    bal = __ballot_sync(0xffffffffu, carry2 + incl >= target);
    int L3 = 31 - __clz(bal);
    unsigned carryn = __shfl_sync(0xffffffffu, incl, (L3 + 1) & 31);
    if (L3 == 31) carryn = 0;
    carryn += carry2;

    if (lane == L3) {
        unsigned b, ab;
        if (carryn + highc >= target) { b = (unsigned)(bbase + 2 * L3 + 1); ab = carryn; }
        else                          { b = (unsigned)(bbase + 2 * L3);     ab = carryn + highc; }
        *s_b = b; *s_above = ab;
    }
}

// general two-pass radix select (fallback rounds only) — exact for arbitrary hi
__device__ unsigned radix_threshold(unsigned* hist, unsigned* s1, unsigned hi, unsigned target,
                                    volatile unsigned* s_b, volatile unsigned* s_above,
                                    volatile int* s_all)
{
    const int tid = threadIdx.x;
    for (int i = tid; i < 8192; i += T) ((uint4*)hist)[i] = make_uint4(0, 0, 0, 0);
    __syncthreads();
    for (int i = tid; i < N_ANCH; i += T) {
        unsigned bits = __float_as_uint(g_nscore[i]);
        if (bits <= hi) {
            unsigned b = bits >> 16;
            atomicAdd(&hist[b >> 1], 1u << ((b & 1) * 16));
        }
    }
    __syncthreads();
    {
        unsigned s = 0;
        #pragma unroll 8
        for (int q = 0; q < 32; q++) { unsigned w = hist[tid * 32 + q]; s += (w & 0xFFFFu) + (w >> 16); }
        s1[tid] = s;
    }
    __syncthreads();
    if (tid < 32) warp_select(hist, s1, target, s_b, s_above, s_all);
    __syncthreads();

    unsigned lo;
    if (*s_all) {
        lo = 0u;
    } else {
        unsigned b1  = *s_b;
        unsigned chi = *s_above;
        __syncthreads();
        for (int i = tid; i < 8192; i += T) ((uint4*)hist)[i] = make_uint4(0, 0, 0, 0);
        __syncthreads();
        for (int i = tid; i < N_ANCH; i += T) {
            unsigned bits = __float_as_uint(g_nscore[i]);
            if (bits <= hi && (bits >> 16) == b1) {
                unsigned b = bits & 0xFFFFu;
                atomicAdd(&hist[b >> 1], 1u << ((b & 1) * 16));
            }
        }
        __syncthreads();
        {
            unsigned s = 0;
            #pragma unroll 8
            for (int q = 0; q < 32; q++) { unsigned w = hist[tid * 32 + q]; s += (w & 0xFFFFu) + (w >> 16); }
            s1[tid] = s;
        }
        __syncthreads();
        if (tid < 32) warp_select(hist, s1, target - chi, s_b, s_above, s_all);
        __syncthreads();
        lo = (*s_all) ? (b1 << 16) : ((b1 << 16) | *s_b);
    }
    __syncthreads();
    return lo;
}

// sort keys[0..S) descending in smem (rank-sort fast path, bitonic fallback)
__device__ void sort_keys(unsigned long long* keys, int S)
{
    const int tid = threadIdx.x;
    if (S <= T) {
        unsigned long long mykey = (tid < S) ? keys[tid] : 0ull;
        int rank = 0;
        if (tid < S) {
            for (int j = 0; j < S; j++) rank += (keys[j] > mykey) ? 1 : 0;
        }
        __syncthreads();
        if (tid < S) keys[rank] = mykey;
        __syncthreads();
    } else {
        int nsort = 1024;
        while (nsort < S) nsort <<= 1;
        for (int i = tid; i < nsort; i += T) if (i >= S) keys[i] = 0ull;
        __syncthreads();
        for (int k = 2; k <= nsort; k <<= 1) {
            for (int j = k >> 1; j > 0; j >>= 1) {
                for (int i = tid; i < nsort; i += T) {
                    int ixj = i ^ j;
                    if (ixj > i) {
                        unsigned long long a = keys[i], b = keys[ixj];
                        bool up = ((i & k) == 0);
                        if (up ? (a < b) : (a > b)) { keys[i] = b; keys[ixj] = a; }
                    }
                }
                __syncthreads();
            }
        }
    }
}

// collect (general, for fallback rounds) + sort
__device__ int collect_sort(unsigned long long* keys, unsigned lo, unsigned hi,
                            volatile unsigned* s_cnt)
{
    const int tid = threadIdx.x;
    if (tid == 0) *s_cnt = 0;
    __syncthreads();
    for (int i = tid; i < N_ANCH; i += T) {
        unsigned bits = __float_as_uint(g_nscore[i]);
        if (bits >= lo && bits <= hi) {
            unsigned p = atomicAdd((unsigned*)s_cnt, 1u);
            if (p < KEYCAP)
                keys[p] = ((unsigned long long)bits << 32) | (0xFFFFFFFFu - (unsigned)i);
        }
    }
    __syncthreads();
    int S = min((int)*s_cnt, KEYCAP);
    sort_keys(keys, S);
    return S;
}

// general (slow-path) chunk processor — candidates beyond the first CH only
__device__ int nms_chunk(int cn, int kept,
                         float4* cbox, float* carea, unsigned* sprev, unsigned* cidx,
                         unsigned* mat, float4* kbox, float* karea, volatile int* s_kept)
{
    const int tid = threadIdx.x;
    const int lane = tid & 31;

    if (kept == 0) {
        for (int c = tid; c < cn; c += T) sprev[c] = 0;
    } else {
        for (int c = tid; c < cn; c += T) {
            float4 b = cbox[c]; float ba = carea[c];
            unsigned f = 0;
            for (int q = 0; q < kept; q++)
                if (iou_sup(kbox[q], karea[q], b, ba)) { f = 1; break; }
            sprev[c] = f;
        }
    }

    for (int iw = tid; iw < CH * 16; iw += T) {
        int i = iw & (CH - 1);
        int w = iw >> 9;
        int j0 = w << 5;
        if (i < cn && j0 < i) {
            float4 bi = cbox[i]; float ai = carea[i];
            int jmax = min(i, j0 + 32);
            unsigned word = 0;
            for (int j = j0; j < jmax; j++)
                if (iou_sup(cbox[j], carea[j], bi, ai)) word |= 1u << (j - j0);
            mat[w * MAT_STRIDE + i] = word;
        } else if (i < cn) {
            mat[w * MAT_STRIDE + i] = 0u;
        }
    }
    __syncthreads();

    if (tid < 32) {
        unsigned km = 0;
        int kp = kept;
        unsigned row = (lane < 16 && cn > 0) ? mat[lane * MAT_STRIDE] : 0u;
        for (int i = 0; i < cn && kp < PAD; i++) {
            unsigned nrow = (lane < 16 && i + 1 < cn) ? mat[lane * MAT_STRIDE + i + 1] : 0u;
            unsigned sp = sprev[i];
            bool clash = __any_sync(0xffffffffu, (row & km) != 0u) || (sp != 0u);
            if (!clash) {
                if (lane == 0) {
                    g_idx[kp]   = (int)cidx[i];
                    g_valid[kp] = 1.0f;
                    g_obox[kp]  = cbox[i];
                    kbox[kp]    = cbox[i];
                    karea[kp]   = carea[i];
                }
                if (lane == (i >> 5)) km |= 1u << (i & 31);
                kp++;
            }
            row = nrow;
        }
        if (lane == 0) *s_kept = kp;
    }
    __syncthreads();
    return *s_kept;
}

// ---------------- output layout ----------------
#define OFF_SC  (PAD * 4)
#define OFF_MK  (OFF_SC + PAD * N_CLS)
#define PER_F4  (MASK_SZ / 4)   // 3969

// ---------------- THE mega-kernel ----------------
__global__ __launch_bounds__(T, 1) void k_mega(
    const float* __restrict__ meta,
    const float* __restrict__ deltas,
    const float* __restrict__ props,
    const float* __restrict__ scores,
    const float* __restrict__ masks,
    float* __restrict__ out)
{
    extern __shared__ char sm[];
    unsigned*           hist  = (unsigned*)(sm);
    float4*             cbox  = (float4*)(sm);
    float*              carea = (float*)(sm + 8192);
    unsigned*           sprev = (unsigned*)(sm + 10240);
    unsigned*           cidx  = (unsigned*)(sm + 12288);
    unsigned*           mat   = (unsigned*)(sm + 14336);
    unsigned*           smat  = (unsigned*)(sm + 47360);   // [16][512] -- resolve only
    unsigned*           scidx = (unsigned*)(sm + 80128);   // [512]
    unsigned long long* keys  = (unsigned long long*)(sm + OFF_KEYS);
    unsigned*           s1    = (unsigned*)(sm + OFF_S1);
    float4*             kbox  = (float4*)(sm + OFF_KBOX);
    float*              karea = (float*)(sm + OFF_KAREA);
    volatile unsigned*  s_cnt   = (volatile unsigned*)(sm + OFF_SCAL);
    volatile int*       s_kept  = (volatile int*)(sm + OFF_SCAL + 4);
    volatile unsigned*  s_b     = (volatile unsigned*)(sm + OFF_SCAL + 8);
    volatile unsigned*  s_above = (volatile unsigned*)(sm + OFF_SCAL + 12);
    volatile int*       s_all   = (volatile int*)(sm + OFF_SCAL + 16);

    const int tid  = threadIdx.x;
    const int lane = tid & 31;
    const int bid  = blockIdx.x;
    const int gtid = bid * T + tid;

    // ========= phase 0: score scan (all blocks, warp per anchor) =========
    {
        int gw = bid * 32 + (tid >> 5);
        for (int a = gw; a < N_ANCH; a += NW) {
            const float* srow = scores + (size_t)a * N_CLS;
            float bv = -INFINITY; int bc = 0;
            float ms = -INFINITY;
            for (int c = lane; c < N_CLS; c += 32) {
                float v = srow[c];
                if (v > bv) { bv = v; bc = c; }
                if (c >= 1) ms = fmaxf(ms, v);
            }
            #pragma unroll
            for (int off = 16; off; off >>= 1) {
                float ov  = __shfl_down_sync(0xffffffffu, bv, off);
                int   oc  = __shfl_down_sync(0xffffffffu, bc, off);
                float oms = __shfl_down_sync(0xffffffffu, ms, off);
                if (ov > bv || (ov == bv && oc < bc)) { bv = ov; bc = oc; }
                ms = fmaxf(ms, oms);
            }
            if (lane == 0) {
                g_nscore[a] = ms;
                g_cls[a]    = bc;
            }
        }
        for (int i = gtid; i < 16 * 512; i += GRID * T) g_mat[i] = 0u;
    }
    signal(&c_dec);

    // ========= phase 1: single-pass select (register-cached) + decode (block 0) =========
    if (bid == 0) {
        spin_ge(&c_dec, GRID);

        // load score bits once into registers
        unsigned mybits[NK];
        #pragma unroll
        for (int k = 0; k < NK; k++) {
            int i = tid + k * T;
            mybits[k] = (i < N_ANCH) ? __float_as_uint(g_nscore[i]) : 0u;
        }

        // fine histogram from registers
        for (int i = tid; i < 8192; i += T) ((uint4*)hist)[i] = make_uint4(0, 0, 0, 0);
        __syncthreads();
        #pragma unroll
        for (int k = 0; k < NK; k++) {
            int i = tid + k * T;
            if (i < N_ANCH) {
                unsigned b = fine_bucket(mybits[k]);
                atomicAdd(&hist[b >> 1], 1u << ((b & 1) * 16));
            }
        }
        __syncthreads();
        {
            unsigned s = 0;
            #pragma unroll 8
            for (int q = 0; q < 32; q++) { unsigned w = hist[tid * 32 + q]; s += (w & 0xFFFFu) + (w >> 16); }
            s1[tid] = s;
        }
        __syncthreads();
        if (tid < 32) warp_select(hist, s1, TARGET, s_b, s_above, s_all);
        __syncthreads();

        unsigned lo;
        if (*s_all) lo = 0u;
        else {
            unsigned b = *s_b;
            lo = (b == 0u) ? 0u : (0x3F000000u + (b << 7));
        }
        __syncthreads();

        // collect from registers
        if (tid == 0) *s_cnt = 0;
        __syncthreads();
        #pragma unroll
        for (int k = 0; k < NK; k++) {
            int i = tid + k * T;
            if (i < N_ANCH && mybits[k] >= lo) {
                unsigned p = atomicAdd((unsigned*)s_cnt, 1u);
                if (p < KEYCAP)
                    keys[p] = ((unsigned long long)mybits[k] << 32) | (0xFFFFFFFFu - (unsigned)i);
            }
        }
        __syncthreads();
        int S = min((int)*s_cnt, KEYCAP);
        sort_keys(keys, S);

        for (int i = tid; i < S; i += T) g_skeys[i] = keys[i];
        int cn = min(S, CH);
        for (int c = tid; c < cn; c += T) {
            int aidx = (int)(0xFFFFFFFFu - (unsigned)keys[c]);
            float4 b = decode_box(aidx, meta, deltas, props);
            g_cbox[c]  = b;
            g_carea[c] = (b.z - b.x + 1.0f) * (b.w - b.y + 1.0f);
        }
        __syncthreads();
        if (tid == 0) { g_S = S; g_lo = lo; __threadfence(); atomicExch(&f_sel, 1); }
        __syncthreads();
    }

    // ========= phase 2: bitmatrix, flat pairs over blocks 1..GRID-1 =========
    spin_ge(&f_sel, 1);
    if (bid != 0) {
        int cn = min(g_S, CH);
        int npair = cn * (cn - 1) / 2;
        for (int p = (bid - 1) * T + tid; p < npair; p += (GRID - 1) * T) {
            float q = sqrtf((float)(8 * p + 1));
            int i = (int)((1.0f + q) * 0.5f);
            while (i * (i - 1) / 2 > p) i--;
            while ((i + 1) * i / 2 <= p) i++;
            int j = p - i * (i - 1) / 2;

            float4 bi = g_cbox[i];
            float4 bj = g_cbox[j];
            float  ai = g_carea[i];
            float  aj = g_carea[j];
            if (iou_sup(bj, aj, bi, ai))
                atomicOr(&g_mat[(j >> 5) * 512 + i], 1u << (j & 31));
        }
    }
    signal(&c_mat);

    // ========= phase 3: resolve (block 0 only) =========
    if (bid == 0) {
        spin_ge(&c_mat, GRID);

        int S = g_S;
        int cn0 = min(S, CH);

        for (int i = tid; i < 2048; i += T) ((uint4*)smat)[i] = ((const uint4*)g_mat)[i];
        for (int i = tid; i < cn0; i += T) scidx[i] = 0xFFFFFFFFu - (unsigned)keys[i];
        if (tid == 0) *s_kept = 0;
        __syncthreads();

        if (tid < 32) {
            unsigned km[16];
            #pragma unroll
            for (int g = 0; g < 16; g++) km[g] = 0u;
            int kp = 0;

            #pragma unroll
            for (int g = 0; g < 16; g++) {
                if (kp >= PAD) break;
                int i = g * 32 + lane;
                bool active = i < cn0;
                unsigned r = active ? smat[g * 512 + i] : 0u;
                unsigned clash = 0;
                #pragma unroll
                for (int w = 0; w < 16; w++) {
                    if (w >= g) break;
                    clash |= (active ? smat[w * 512 + i] : 0u) & km[w];
                }
                unsigned myidx = active ? scidx[i] : 0u;

                unsigned activeM  = __ballot_sync(0xffffffffu, active);
                unsigned suspects = __ballot_sync(0xffffffffu, active && ((r != 0u) || (clash != 0u)));

                unsigned kmg;
                if (suspects == 0u) {
                    kmg = activeM;
                } else {
                    kmg = activeM & ~suspects;
                    unsigned rem = suspects;
                    while (rem) {
                        int t = __ffs(rem) - 1; rem &= rem - 1;
                        unsigned rt = __shfl_sync(0xffffffffu, r, t);
                        unsigned ct = __shfl_sync(0xffffffffu, clash, t);
                        if (ct == 0u && (rt & kmg) == 0u) kmg |= 1u << t;
                    }
                }

                int allowed = PAD - kp;
                int cnt = __popc(kmg);
                int rank = __popc(kmg & ((1u << lane) - 1u));
                bool mykeep = ((kmg >> lane) & 1u) && (rank < allowed);
                if (mykeep) {
                    g_idx[kp + rank]   = (int)myidx;
                    g_valid[kp + rank] = 1.0f;
                    g_obox[kp + rank]  = g_cbox[i];
                }
                km[g] = __ballot_sync(0xffffffffu, mykeep);
                kp += min(cnt, allowed);
            }
            if (lane == 0) *s_kept = kp;
        }
        __syncthreads();
        int kept = *s_kept;

        // general fallback (rare): more chunks / further radix rounds
        if (kept < PAD && (S > CH || g_lo > 0)) {
            for (int q = tid; q < kept; q += T) {
                float4 b = g_obox[q];
                kbox[q] = b;
                karea[q] = (b.z - b.x + 1.0f) * (b.w - b.y + 1.0f);
            }
            __syncthreads();

            for (int base = CH; base < S && kept < PAD; base += CH) {
                int cn = min(CH, S - base);
                for (int c = tid; c < cn; c += T) {
                    int aidx = (int)(0xFFFFFFFFu - (unsigned)g_skeys[base + c]);
                    cidx[c] = (unsigned)aidx;
                    float4 b = decode_box(aidx, meta, deltas, props);
                    cbox[c] = b;
                    carea[c] = (b.z - b.x + 1.0f) * (b.w - b.y + 1.0f);
                }
                __syncthreads();
                kept = nms_chunk(cn, kept, cbox, carea, sprev, cidx, mat,
                                 kbox, karea, s_kept);
            }

            if (kept < PAD && g_lo > 0) {
                unsigned hi = g_lo - 1u;
                while (kept < PAD) {
                    unsigned lo = radix_threshold(hist, s1, hi, TARGET, s_b, s_above, s_all);
                    int Sb = collect_sort(keys, lo, hi, s_cnt);
                    for (int base = 0; base < Sb && kept < PAD; base += CH) {
                        int cn = min(CH, Sb - base);
                        for (int c = tid; c < cn; c += T) {
                            int aidx = (int)(0xFFFFFFFFu - (unsigned)keys[base + c]);
                            cidx[c] = (unsigned)aidx;
                            float4 b = decode_box(aidx, meta, deltas, props);
                            cbox[c] = b;
                            carea[c] = (b.z - b.x + 1.0f) * (b.w - b.y + 1.0f);
                        }
                        __syncthreads();
                        kept = nms_chunk(cn, kept, cbox, carea, sprev, cidx, mat,
                                         kbox, karea, s_kept);
                    }
                    if (lo == 0u) break;
                    hi = lo - 1u;
                    __syncthreads();
                }
            }
        }

        for (int r = kept + tid; r < PAD; r += T) { g_idx[r] = 0; g_valid[r] = 0.0f; }
        __syncthreads();
        if (tid == 0) { __threadfence(); atomicExch(&f_res, 1); }
        __syncthreads();
    }

    // ========= phase 4: gather (all blocks) =========
    spin_ge(&f_res, 1);
    {
        for (int d = bid; d < PAD; d += GRID) {
            int idx = g_idx[d];
            float s = g_valid[d];
            const float4* src = (const float4*)(masks + (size_t)idx * MASK_SZ);
            float4* dst = (float4*)(out + OFF_MK) + (size_t)d * PER_F4;
            for (int m = tid; m < PER_F4; m += T) {
                float4 v = src[m];
                v.x *= s; v.y *= s; v.z *= s; v.w *= s;
                dst[m] = v;
            }
        }
        if (gtid < OFF_MK) {
            int e = gtid;
            if (e < OFF_SC) {
                int k = e >> 2, c = e & 3;
                const float* bp = (const float*)&g_obox[k];
                out[e] = bp[c] * g_valid[k];
            } else {
                int r = e - OFF_SC;
                int k = r / N_CLS, c = r - k * N_CLS;
                out[e] = scores[(size_t)g_idx[k] * N_CLS + c] * g_valid[k];
            }
        }
    }
    signal(&c_fin);

    // ========= phase 5: reset counters for next graph replay =========
    if (bid == 0) {
        if (tid == 0) {
            while (*(volatile int*)&c_fin < GRID) __nanosleep(64);
            c_dec = 0; f_sel = 0; c_mat = 0; f_res = 0; c_fin = 0;
            __threadfence();
        }
    }
}

// ---------------- launch ----------------
extern "C" void kernel_launch(void* const* d_in, const int* in_sizes, int n_in,
                              void* d_out, int out_size)
{
    const float* meta   = (const float*)d_in[0];
    const float* deltas = (const float*)d_in[1];
    const float* props  = (const float*)d_in[2];
    const float* scores = (const float*)d_in[3];
    const float* masks  = (const float*)d_in[4];
    float* out = (float*)d_out;

    static bool attr_done = false;
    if (!attr_done) {
        cudaFuncSetAttribute(k_mega, cudaFuncAttributeMaxDynamicSharedMemorySize, SMEM_TOTAL);
        attr_done = true;
    }

    k_mega<<<GRID, T, SMEM_TOTAL>>>(meta, deltas, props, scores, masks, out);
}

// round 17
// speedup vs baseline: 1.4438x; 1.0098x over previous
#include <cuda_runtime.h>
#include <cuda_bf16.h>
#include <math.h>

#define N_ANCH 6000
#define N_CLS  81
#define PAD    300
#define MASK_SZ (14*14*81)   // 15876
#define NMS_THRESH 0.5f
#define T      1024
#define GRID   120
#define NW     (GRID * 32)
#define TARGET 384u
#define KEYCAP 8192
#define CH     512
#define MAT_STRIDE 516
#define NK     ((N_ANCH + T - 1) / T)   // 6 score slots per thread

// ---- dynamic smem layout (bytes) ----
#define OFF_KEYS  131072   // u64[8192]  (65536) -> 196608
#define OFF_S1    196608   // u32[1024]  (4096)  -> 200704
#define OFF_KBOX  200704   // float4[300](4800)  -> 205504
#define OFF_KAREA 205504   // f32[300]   (1200)  -> 206704
#define OFF_SCAL  206704
#define SMEM_TOTAL 206848
// region A aliases (strict phase lifetimes):
//   hist u32[32768]@0 (131072)          -- block-0 select ONLY
//   cbox f4[512]@0 | carea f32[512]@8192 | sprev u32[512]@10240
//   cidx u32[512]@12288 | mat u32[16*516]@14336 (33024)   -- fallback chunks
//   smat u32[16*512]@47360 (32768) | scidx u32[512]@80128 -- resolve ONLY

// ---------------- scratch (device globals, no allocation) ----------------
__device__ float  g_nscore[N_ANCH];
__device__ int    g_cls[N_ANCH];
__device__ unsigned long long g_skeys[KEYCAP];
__device__ float4 g_cbox[CH];
__device__ float  g_carea[CH];
__device__ int      g_S;
__device__ unsigned g_lo;
__device__ unsigned g_mat[16 * 512];
__device__ int    g_idx[PAD];
__device__ float  g_valid[PAD];
__device__ float4 g_obox[PAD];
__device__ int c_dec, f_sel, c_mat, f_res, c_fin;

__device__ __forceinline__ void spin_ge(int* c, int v)
{
    if (threadIdx.x == 0) {
        while (*(volatile int*)c < v) __nanosleep(64);
        __threadfence();
    }
    __syncthreads();
}
__device__ __forceinline__ void signal(int* c)
{
    __syncthreads();
    if (threadIdx.x == 0) { __threadfence(); atomicAdd(c, 1); }
}

__device__ __forceinline__ bool iou_sup(float4 a, float aa, float4 b, float ba)
{
    float xx1 = fmaxf(a.x, b.x);
    float yy1 = fmaxf(a.y, b.y);
    float xx2 = fminf(a.z, b.z);
    float yy2 = fminf(a.w, b.w);
    float iw = fmaxf(xx2 - xx1 + 1.0f, 0.0f);
    float ih = fmaxf(yy2 - yy1 + 1.0f, 0.0f);
    float inter = iw * ih;
    return inter / (aa + ba - inter) > NMS_THRESH;
}

__device__ __forceinline__ float4 decode_box(int a,
    const float* __restrict__ meta,
    const float* __restrict__ deltas,
    const float* __restrict__ props)
{
    float H = meta[0], W = meta[1], scale = meta[2];
    const float* p = props + (size_t)a * 4;
    float x1 = p[0] / scale, y1 = p[1] / scale;
    float x2 = p[2] / scale, y2 = p[3] / scale;
    float w  = x2 - x1 + 1.0f, h = y2 - y1 + 1.0f;
    float cx = x1 + 0.5f * w, cy = y1 + 0.5f * h;

    int bc = g_cls[a];
    const float* d = deltas + (size_t)a * (4 * N_CLS) + bc * 4;
    float pcx = d[0] * w + cx;
    float pcy = d[1] * h + cy;
    float pw  = expf(d[2]) * w;
    float ph  = expf(d[3]) * h;

    float px1 = pcx - 0.5f * pw, py1 = pcy - 0.5f * ph;
    float px2 = pcx + 0.5f * pw, py2 = pcy + 0.5f * ph;
    px1 = fminf(fmaxf(px1, 0.0f), W - 1.0f);
    py1 = fminf(fmaxf(py1, 0.0f), H - 1.0f);
    px2 = fminf(fmaxf(px2, 0.0f), W - 1.0f);
    py2 = fminf(fmaxf(py2, 0.0f), H - 1.0f);
    return make_float4(px1, py1, px2, py2);
}

// fine bucket for single-pass first select: mantissa bits [22:7] of scores in
// [0.5, 1.0); clamped outside. Monotone in score bits by construction.
__device__ __forceinline__ unsigned fine_bucket(unsigned bits)
{
    if (bits >= 0x3F800000u) return 65535u;
    if (bits <  0x3F000000u) return 0u;
    return (bits >> 7) - 0x7E0000u;
}

// warp-0 hierarchical suffix search over 65536-bucket histogram.
__device__ __forceinline__ void warp_select(const unsigned* hist, const unsigned* s1,
                                            unsigned target,
                                            volatile unsigned* s_b,
                                            volatile unsigned* s_above,
                                            volatile int* s_all)
{
    int lane = threadIdx.x;

    unsigned s2 = 0;
    #pragma unroll 8
    for (int q = 0; q < 32; q++) s2 += s1[lane * 32 + q];
    unsigned incl = s2;
    #pragma unroll
    for (int off = 1; off < 32; off <<= 1) {
        unsigned v = __shfl_down_sync(0xffffffffu, incl, off);
        if (lane + off < 32) incl += v;
    }
    unsigned total = __shfl_sync(0xffffffffu, incl, 0);
    if (total < target) { if (lane == 0) *s_all = 1; return; }
    if (lane == 0) *s_all = 0;

    unsigned bal = __ballot_sync(0xffffffffu, incl >= target);
    int L1 = 31 - __clz(bal);
    unsigned carry1 = __shfl_sync(0xffffffffu, incl, (L1 + 1) & 31);
    if (L1 == 31) carry1 = 0;

    incl = s1[L1 * 32 + lane];
    #pragma unroll
    for (int off = 1; off < 32; off <<= 1) {
        unsigned v = __shfl_down_sync(0xffffffffu, incl, off);
        if (lane + off < 32) incl += v;
    }
    bal = __ballot_sync(0xffffffffu, carry1 + incl >= target);
    int L2 = 31 - __clz(bal);
    unsigned carry2 = __shfl_sync(0xffffffffu, incl, (L2 + 1) & 31);
    if (L2 == 31) carry2 = 0;
    carry2 += carry1;

    int bbase = (L1 * 32 + L2) * 64;
    unsigned w = hist[(bbase >> 1) + lane];
    unsigned lowc = w & 0xFFFFu, highc = w >> 16;
    incl = lowc + highc;
    #pragma unroll
    for (int off = 1; off < 32; off <<= 1) {
        unsigned v = __shfl_down_sync(0xffffffffu, incl, off);
        if (lane + off < 32) incl += v;
    }
    bal = __ballot_sync(0xffffffffu, carry2 + incl >= target);
    int L3 = 31 - __clz(bal);
    unsigned carryn = __shfl_sync(0xffffffffu, incl, (L3 + 1) & 31);
    if (L3 == 31) carryn = 0;
    carryn += carry2;

    if (lane == L3) {
        unsigned b, ab;
        if (carryn + highc >= target) { b = (unsigned)(bbase + 2 * L3 + 1); ab = carryn; }
        else                          { b = (unsigned)(bbase + 2 * L3);     ab = carryn + highc; }
        *s_b = b; *s_above = ab;
    }
}

// general two-pass radix select (fallback rounds only) — exact for arbitrary hi
__device__ unsigned radix_threshold(unsigned* hist, unsigned* s1, unsigned hi, unsigned target,
                                    volatile unsigned* s_b, volatile unsigned* s_above,
                                    volatile int* s_all)
{
    const int tid = threadIdx.x;
    for (int i = tid; i < 8192; i += T) ((uint4*)hist)[i] = make_uint4(0, 0, 0, 0);
    __syncthreads();
    for (int i = tid; i < N_ANCH; i += T) {
        unsigned bits = __float_as_uint(g_nscore[i]);
        if (bits <= hi) {
            unsigned b = bits >> 16;
            atomicAdd(&hist[b >> 1], 1u << ((b & 1) * 16));
        }
    }
    __syncthreads();
    {
        unsigned s = 0;
        #pragma unroll 8
        for (int q = 0; q < 32; q++) { unsigned w = hist[tid * 32 + q]; s += (w & 0xFFFFu) + (w >> 16); }
        s1[tid] = s;
    }
    __syncthreads();
    if (tid < 32) warp_select(hist, s1, target, s_b, s_above, s_all);
    __syncthreads();

    unsigned lo;
    if (*s_all) {
        lo = 0u;
    } else {
        unsigned b1  = *s_b;
        unsigned chi = *s_above;
        __syncthreads();
        for (int i = tid; i < 8192; i += T) ((uint4*)hist)[i] = make_uint4(0, 0, 0, 0);
        __syncthreads();
        for (int i = tid; i < N_ANCH; i += T) {
            unsigned bits = __float_as_uint(g_nscore[i]);
            if (bits <= hi && (bits >> 16) == b1) {
                unsigned b = bits & 0xFFFFu;
                atomicAdd(&hist[b >> 1], 1u << ((b & 1) * 16));
            }
        }
        __syncthreads();
        {
            unsigned s = 0;
            #pragma unroll 8
            for (int q = 0; q < 32; q++) { unsigned w = hist[tid * 32 + q]; s += (w & 0xFFFFu) + (w >> 16); }
            s1[tid] = s;
        }
        __syncthreads();
        if (tid < 32) warp_select(hist, s1, target - chi, s_b, s_above, s_all);
        __syncthreads();
        lo = (*s_all) ? (b1 << 16) : ((b1 << 16) | *s_b);
    }
    __syncthreads();
    return lo;
}

// sort keys[0..S) descending in smem (rank-sort fast path, bitonic fallback)
__device__ void sort_keys(unsigned long long* keys, int S)
{
    const int tid = threadIdx.x;
    if (S <= T) {
        unsigned long long mykey = (tid < S) ? keys[tid] : 0ull;
        int rank = 0;
        if (tid < S) {
            for (int j = 0; j < S; j++) rank += (keys[j] > mykey) ? 1 : 0;
        }
        __syncthreads();
        if (tid < S) keys[rank] = mykey;
        __syncthreads();
    } else {
        int nsort = 1024;
        while (nsort < S) nsort <<= 1;
        for (int i = tid; i < nsort; i += T) if (i >= S) keys[i] = 0ull;
        __syncthreads();
        for (int k = 2; k <= nsort; k <<= 1) {
            for (int j = k >> 1; j > 0; j >>= 1) {
                for (int i = tid; i < nsort; i += T) {
                    int ixj = i ^ j;
                    if (ixj > i) {
                        unsigned long long a = keys[i], b = keys[ixj];
                        bool up = ((i & k) == 0);
                        if (up ? (a < b) : (a > b)) { keys[i] = b; keys[ixj] = a; }
                    }
                }
                __syncthreads();
            }
        }
    }
}

// collect (general, for fallback rounds) + sort
__device__ int collect_sort(unsigned long long* keys, unsigned lo, unsigned hi,
                            volatile unsigned* s_cnt)
{
    const int tid = threadIdx.x;
    if (tid == 0) *s_cnt = 0;
    __syncthreads();
    for (int i = tid; i < N_ANCH; i += T) {
        unsigned bits = __float_as_uint(g_nscore[i]);
        if (bits >= lo && bits <= hi) {
            unsigned p = atomicAdd((unsigned*)s_cnt, 1u);
            if (p < KEYCAP)
                keys[p] = ((unsigned long long)bits << 32) | (0xFFFFFFFFu - (unsigned)i);
        }
    }
    __syncthreads();
    int S = min((int)*s_cnt, KEYCAP);
    sort_keys(keys, S);
    return S;
}

// general (slow-path) chunk processor — candidates beyond the first CH only
__device__ int nms_chunk(int cn, int kept,
                         float4* cbox, float* carea, unsigned* sprev, unsigned* cidx,
                         unsigned* mat, float4* kbox, float* karea, volatile int* s_kept)
{
    const int tid = threadIdx.x;
    const int lane = tid & 31;

    if (kept == 0) {
        for (int c = tid; c < cn; c += T) sprev[c] = 0;
    } else {
        for (int c = tid; c < cn; c += T) {
            float4 b = cbox[c]; float ba = carea[c];
            unsigned f = 0;
            for (int q = 0; q < kept; q++)
                if (iou_sup(kbox[q], karea[q], b, ba)) { f = 1; break; }
            sprev[c] = f;
        }
    }

    for (int iw = tid; iw < CH * 16; iw += T) {
        int i = iw & (CH - 1);
        int w = iw >> 9;
        int j0 = w << 5;
        if (i < cn && j0 < i) {
            float4 bi = cbox[i]; float ai = carea[i];
            int jmax = min(i, j0 + 32);
            unsigned word = 0;
            for (int j = j0; j < jmax; j++)
                if (iou_sup(cbox[j], carea[j], bi, ai)) word |= 1u << (j - j0);
            mat[w * MAT_STRIDE + i] = word;
        } else if (i < cn) {
            mat[w * MAT_STRIDE + i] = 0u;
        }
    }
    __syncthreads();

    if (tid < 32) {
        unsigned km = 0;
        int kp = kept;
        unsigned row = (lane < 16 && cn > 0) ? mat[lane * MAT_STRIDE] : 0u;
        for (int i = 0; i < cn && kp < PAD; i++) {
            unsigned nrow = (lane < 16 && i + 1 < cn) ? mat[lane * MAT_STRIDE + i + 1] : 0u;
            unsigned sp = sprev[i];
            bool clash = __any_sync(0xffffffffu, (row & km) != 0u) || (sp != 0u);
            if (!clash) {
                if (lane == 0) {
                    g_idx[kp]   = (int)cidx[i];
                    g_valid[kp] = 1.0f;
                    g_obox[kp]  = cbox[i];
                    kbox[kp]    = cbox[i];
                    karea[kp]   = carea[i];
                }
                if (lane == (i >> 5)) km |= 1u << (i & 31);
                kp++;
            }
            row = nrow;
        }
        if (lane == 0) *s_kept = kp;
    }
    __syncthreads();
    return *s_kept;
}

// ---------------- output layout ----------------
#define OFF_SC  (PAD * 4)
#define OFF_MK  (OFF_SC + PAD * N_CLS)
#define PER_F4  (MASK_SZ / 4)   // 3969
#define MK_F4   (PAD * PER_F4)  // 1190700

// ---------------- THE mega-kernel ----------------
__global__ __launch_bounds__(T, 1) void k_mega(
    const float* __restrict__ meta,
    const float* __restrict__ deltas,
    const float* __restrict__ props,
    const float* __restrict__ scores,
    const float* __restrict__ masks,
    float* __restrict__ out)
{
    extern __shared__ char sm[];
    unsigned*           hist  = (unsigned*)(sm);
    float4*             cbox  = (float4*)(sm);
    float*              carea = (float*)(sm + 8192);
    unsigned*           sprev = (unsigned*)(sm + 10240);
    unsigned*           cidx  = (unsigned*)(sm + 12288);
    unsigned*           mat   = (unsigned*)(sm + 14336);
    unsigned*           smat  = (unsigned*)(sm + 47360);   // [16][512] -- resolve only
    unsigned*           scidx = (unsigned*)(sm + 80128);   // [512]
    unsigned long long* keys  = (unsigned long long*)(sm + OFF_KEYS);
    unsigned*           s1    = (unsigned*)(sm + OFF_S1);
    float4*             kbox  = (float4*)(sm + OFF_KBOX);
    float*              karea = (float*)(sm + OFF_KAREA);
    volatile unsigned*  s_cnt   = (volatile unsigned*)(sm + OFF_SCAL);
    volatile int*       s_kept  = (volatile int*)(sm + OFF_SCAL + 4);
    volatile unsigned*  s_b     = (volatile unsigned*)(sm + OFF_SCAL + 8);
    volatile unsigned*  s_above = (volatile unsigned*)(sm + OFF_SCAL + 12);
    volatile int*       s_all   = (volatile int*)(sm + OFF_SCAL + 16);

    const int tid  = threadIdx.x;
    const int lane = tid & 31;
    const int bid  = blockIdx.x;
    const int gtid = bid * T + tid;

    // ========= phase 0: score scan (all blocks, warp per anchor) =========
    {
        int gw = bid * 32 + (tid >> 5);
        for (int a = gw; a < N_ANCH; a += NW) {
            const float* srow = scores + (size_t)a * N_CLS;
            float bv = -INFINITY; int bc = 0;
            float ms = -INFINITY;
            for (int c = lane; c < N_CLS; c += 32) {
                float v = srow[c];
                if (v > bv) { bv = v; bc = c; }
                if (c >= 1) ms = fmaxf(ms, v);
            }
            #pragma unroll
            for (int off = 16; off; off >>= 1) {
                float ov  = __shfl_down_sync(0xffffffffu, bv, off);
                int   oc  = __shfl_down_sync(0xffffffffu, bc, off);
                float oms = __shfl_down_sync(0xffffffffu, ms, off);
                if (ov > bv || (ov == bv && oc < bc)) { bv = ov; bc = oc; }
                ms = fmaxf(ms, oms);
            }
            if (lane == 0) {
                g_nscore[a] = ms;
                g_cls[a]    = bc;
            }
        }
        for (int i = gtid; i < 16 * 512; i += GRID * T) g_mat[i] = 0u;
    }
    signal(&c_dec);

    // ========= phase 1: single-pass select (register-cached) + decode (block 0) =========
    if (bid == 0) {
        spin_ge(&c_dec, GRID);

        unsigned mybits[NK];
        #pragma unroll
        for (int k = 0; k < NK; k++) {
            int i = tid + k * T;
            mybits[k] = (i < N_ANCH) ? __float_as_uint(g_nscore[i]) : 0u;
        }

        for (int i = tid; i < 8192; i += T) ((uint4*)hist)[i] = make_uint4(0, 0, 0, 0);
        __syncthreads();
        #pragma unroll
        for (int k = 0; k < NK; k++) {
            int i = tid + k * T;
            if (i < N_ANCH) {
                unsigned b = fine_bucket(mybits[k]);
                atomicAdd(&hist[b >> 1], 1u << ((b & 1) * 16));
            }
        }
        __syncthreads();
        {
            unsigned s = 0;
            #pragma unroll 8
            for (int q = 0; q < 32; q++) { unsigned w = hist[tid * 32 + q]; s += (w & 0xFFFFu) + (w >> 16); }
            s1[tid] = s;
        }
        __syncthreads();
        if (tid < 32) warp_select(hist, s1, TARGET, s_b, s_above, s_all);
        __syncthreads();

        unsigned lo;
        if (*s_all) lo = 0u;
        else {
            unsigned b = *s_b;
            lo = (b == 0u) ? 0u : (0x3F000000u + (b << 7));
        }
        __syncthreads();

        if (tid == 0) *s_cnt = 0;
        __syncthreads();
        #pragma unroll
        for (int k = 0; k < NK; k++) {
            int i = tid + k * T;
            if (i < N_ANCH && mybits[k] >= lo) {
                unsigned p = atomicAdd((unsigned*)s_cnt, 1u);
                if (p < KEYCAP)
                    keys[p] = ((unsigned long long)mybits[k] << 32) | (0xFFFFFFFFu - (unsigned)i);
            }
        }
        __syncthreads();
        int S = min((int)*s_cnt, KEYCAP);
        sort_keys(keys, S);

        for (int i = tid; i < S; i += T) g_skeys[i] = keys[i];
        int cn = min(S, CH);
        for (int c = tid; c < cn; c += T) {
            int aidx = (int)(0xFFFFFFFFu - (unsigned)keys[c]);
            float4 b = decode_box(aidx, meta, deltas, props);
            g_cbox[c]  = b;
            g_carea[c] = (b.z - b.x + 1.0f) * (b.w - b.y + 1.0f);
        }
        __syncthreads();
        if (tid == 0) { g_S = S; g_lo = lo; __threadfence(); atomicExch(&f_sel, 1); }
        __syncthreads();
    }

    // ========= phase 2: bitmatrix, flat pairs over blocks 1..GRID-1 =========
    spin_ge(&f_sel, 1);
    if (bid != 0) {
        int cn = min(g_S, CH);
        int npair = cn * (cn - 1) / 2;
        for (int p = (bid - 1) * T + tid; p < npair; p += (GRID - 1) * T) {
            float q = sqrtf((float)(8 * p + 1));
            int i = (int)((1.0f + q) * 0.5f);
            while (i * (i - 1) / 2 > p) i--;
            while ((i + 1) * i / 2 <= p) i++;
            int j = p - i * (i - 1) / 2;

            float4 bi = g_cbox[i];
            float4 bj = g_cbox[j];
            float  ai = g_carea[i];
            float  aj = g_carea[j];
            if (iou_sup(bj, aj, bi, ai))
                atomicOr(&g_mat[(j >> 5) * 512 + i], 1u << (j & 31));
        }
    }
    signal(&c_mat);

    // ========= phase 3: resolve (block 0 only) =========
    if (bid == 0) {
        spin_ge(&c_mat, GRID);

        int S = g_S;
        int cn0 = min(S, CH);

        for (int i = tid; i < 2048; i += T) ((uint4*)smat)[i] = ((const uint4*)g_mat)[i];
        for (int i = tid; i < cn0; i += T) scidx[i] = 0xFFFFFFFFu - (unsigned)keys[i];
        if (tid == 0) *s_kept = 0;
        __syncthreads();

        if (tid < 32) {
            unsigned km[16];
            #pragma unroll
            for (int g = 0; g < 16; g++) km[g] = 0u;
            int kp = 0;

            #pragma unroll
            for (int g = 0; g < 16; g++) {
                if (kp >= PAD) break;
                int i = g * 32 + lane;
                bool active = i < cn0;
                unsigned r = active ? smat[g * 512 + i] : 0u;
                unsigned clash = 0;
                #pragma unroll
                for (int w = 0; w < 16; w++) {
                    if (w >= g) break;
                    clash |= (active ? smat[w * 512 + i] : 0u) & km[w];
                }
                unsigned myidx = active ? scidx[i] : 0u;

                unsigned activeM  = __ballot_sync(0xffffffffu, active);
                unsigned suspects = __ballot_sync(0xffffffffu, active && ((r != 0u) || (clash != 0u)));

                unsigned kmg;
                if (suspects == 0u) {
                    kmg = activeM;
                } else {
                    kmg = activeM & ~suspects;
                    unsigned rem = suspects;
                    while (rem) {
                        int t = __ffs(rem) - 1; rem &= rem - 1;
                        unsigned rt = __shfl_sync(0xffffffffu, r, t);
                        unsigned ct = __shfl_sync(0xffffffffu, clash, t);
                        if (ct == 0u && (rt & kmg) == 0u) kmg |= 1u << t;
                    }
                }

                int allowed = PAD - kp;
                int cnt = __popc(kmg);
                int rank = __popc(kmg & ((1u << lane) - 1u));
                bool mykeep = ((kmg >> lane) & 1u) && (rank < allowed);
                if (mykeep) {
                    g_idx[kp + rank]   = (int)myidx;
                    g_valid[kp + rank] = 1.0f;
                    g_obox[kp + rank]  = g_cbox[i];
                }
                km[g] = __ballot_sync(0xffffffffu, mykeep);
                kp += min(cnt, allowed);
            }
            if (lane == 0) *s_kept = kp;
        }
        __syncthreads();
        int kept = *s_kept;

        // general fallback (rare): more chunks / further radix rounds
        if (kept < PAD && (S > CH || g_lo > 0)) {
            for (int q = tid; q < kept; q += T) {
                float4 b = g_obox[q];
                kbox[q] = b;
                karea[q] = (b.z - b.x + 1.0f) * (b.w - b.y + 1.0f);
            }
            __syncthreads();

            for (int base = CH; base < S && kept < PAD; base += CH) {
                int cn = min(CH, S - base);
                for (int c = tid; c < cn; c += T) {
                    int aidx = (int)(0xFFFFFFFFu - (unsigned)g_skeys[base + c]);
                    cidx[c] = (unsigned)aidx;
                    float4 b = decode_box(aidx, meta, deltas, props);
                    cbox[c] = b;
                    carea[c] = (b.z - b.x + 1.0f) * (b.w - b.y + 1.0f);
                }
                __syncthreads();
                kept = nms_chunk(cn, kept, cbox, carea, sprev, cidx, mat,
                                 kbox, karea, s_kept);
            }

            if (kept < PAD && g_lo > 0) {
                unsigned hi = g_lo - 1u;
                while (kept < PAD) {
                    unsigned lo = radix_threshold(hist, s1, hi, TARGET, s_b, s_above, s_all);
                    int Sb = collect_sort(keys, lo, hi, s_cnt);
                    for (int base = 0; base < Sb && kept < PAD; base += CH) {
                        int cn = min(CH, Sb - base);
                        for (int c = tid; c < cn; c += T) {
                            int aidx = (int)(0xFFFFFFFFu - (unsigned)keys[base + c]);
                            cidx[c] = (unsigned)aidx;
                            float4 b = decode_box(aidx, meta, deltas, props);
                            cbox[c] = b;
                            carea[c] = (b.z - b.x + 1.0f) * (b.w - b.y + 1.0f);
                        }
                        __syncthreads();
                        kept = nms_chunk(cn, kept, cbox, carea, sprev, cidx, mat,
                                         kbox, karea, s_kept);
                    }
                    if (lo == 0u) break;
                    hi = lo - 1u;
                    __syncthreads();
                }
            }
        }

        for (int r = kept + tid; r < PAD; r += T) { g_idx[r] = 0; g_valid[r] = 0.0f; }
        __syncthreads();
        if (tid == 0) { __threadfence(); atomicExch(&f_res, 1); }
        __syncthreads();
    }

    // ========= phase 4: gather (all blocks, flat balanced, streaming hints) =========
    spin_ge(&f_res, 1);
    {
        // masks: flat grid-stride over all float4s — perfect balance, high MLP
        float4* dst = (float4*)(out + OFF_MK);
        for (int e = gtid; e < MK_F4; e += GRID * T) {
            int k = e / PER_F4;                 // constant division -> mul/shift
            int m = e - k * PER_F4;
            const float4* src = (const float4*)(masks + (size_t)g_idx[k] * MASK_SZ);
            float4 v = __ldcs(&src[m]);
            float s = g_valid[k];
            v.x *= s; v.y *= s; v.z *= s; v.w *= s;
            __stcs(&dst[e], v);
        }
        // boxes + scores: single pass, first 24600 global threads
        if (gtid < OFF_MK) {
            int e = gtid;
            if (e < OFF_SC) {
                int k = e >> 2, c = e & 3;
                const float* bp = (const float*)&g_obox[k];
                out[e] = bp[c] * g_valid[k];
            } else {
                int r = e - OFF_SC;
                int k = r / N_CLS, c = r - k * N_CLS;
                out[e] = scores[(size_t)g_idx[k] * N_CLS + c] * g_valid[k];
            }
        }
    }
    signal(&c_fin);

    // ========= phase 5: reset counters for next graph replay =========
    if (bid == 0) {
        if (tid == 0) {
            while (*(volatile int*)&c_fin < GRID) __nanosleep(64);
            c_dec = 0; f_sel = 0; c_mat = 0; f_res = 0; c_fin = 0;
            __threadfence();
        }
    }
}

// ---------------- launch ----------------
extern "C" void kernel_launch(void* const* d_in, const int* in_sizes, int n_in,
                              void* d_out, int out_size)
{
    const float* meta   = (const float*)d_in[0];
    const float* deltas = (const float*)d_in[1];
    const float* props  = (const float*)d_in[2];
    const float* scores = (const float*)d_in[3];
    const float* masks  = (const float*)d_in[4];
    float* out = (float*)d_out;

    static bool attr_done = false;
    if (!attr_done) {
        cudaFuncSetAttribute(k_mega, cudaFuncAttributeMaxDynamicSharedMemorySize, SMEM_TOTAL);
        attr_done = true;
    }

    k_mega<<<GRID, T, SMEM_TOTAL>>>(meta, deltas, props, scores, masks, out);
}